// round 4
// baseline (speedup 1.0000x reference)
#include <cuda_runtime.h>
#include <cuda_bf16.h>
#include <cstdint>

#define Bq 256      // queries
#define Dk 768      // feature dim
#define Nn 131072   // database rows
#define Lo 512      // output row length

// ---------------- arch feature detection ----------------
#if defined(__CUDA_ARCH_FEAT_SM103_ALL) || defined(__CUDA_ARCH_FEAT_SM100_ALL) || \
    (defined(__CUDA_ARCH_SPECIFIC__) && (__CUDA_ARCH_SPECIFIC__ >= 1000)) ||      \
    (defined(__CUDA_ARCH_FAMILY_SPECIFIC__) && (__CUDA_ARCH_FAMILY_SPECIFIC__ >= 1000))
#define USE_TCGEN05 1
#else
#define USE_TCGEN05 0
#endif

#define SMEM_TOTAL 198656

__device__ __nv_bfloat16 g_qh[Bq * Dk];
__device__ float g_invn[Nn];
__device__ __nv_bfloat16 g_sims[(size_t)Bq * Nn];   // 67 MB scratch
__device__ unsigned long long g_best[Bq];           // pass1 bf16 max (threshold)
__device__ unsigned long long g_best2[Bq];          // pass2 exact argmax

// ---------------- common helpers ----------------
__device__ __forceinline__ uint32_t smem_u32(const void* p) {
    uint32_t a;
    asm("{ .reg .u64 t; cvta.to.shared.u64 t, %1; cvt.u32.u64 %0, t; }"
        : "=r"(a) : "l"(p));
    return a;
}
__device__ __forceinline__ unsigned long long pack_key(float v, unsigned idx) {
    unsigned u = __float_as_uint(v);
    u = (u & 0x80000000u) ? ~u : (u | 0x80000000u);
    return ((unsigned long long)u << 32) | (unsigned)(~idx);
}
__device__ __forceinline__ float unpack_val(unsigned long long k) {
    unsigned s = (unsigned)(k >> 32);
    unsigned u = (s & 0x80000000u) ? (s & 0x7fffffffu) : ~s;
    return __uint_as_float(u);
}
__device__ __forceinline__ uint32_t b2u(__nv_bfloat162 h) {
    return *reinterpret_cast<uint32_t*>(&h);
}

// ---------------- init ----------------
__global__ void init_kernel() {
    g_best[threadIdx.x] = 0ull;
    g_best2[threadIdx.x] = 0ull;
}

// ---------------- query bf16 precompute ----------------
__global__ void convert_q_kernel(const float* __restrict__ x) {
    int i = blockIdx.x * 256 + threadIdx.x;
    g_qh[i] = __float2bfloat16(x[i]);
}

#if USE_TCGEN05
// ============================================================================
// tcgen05 path
// ============================================================================
#define TILE_N 256
#define KC 64
#define NCHUNK 12

#define SM_TMEM   0
#define SM_MBAR0  8
#define SM_MBAR1  16
#define SM_INVN   32
#define SM_BUF    2048
#define BUF_QH    0
#define BUF_DH    16384
#define BUF_SIZE  49152

#define IDESC 0x8400490u   // dtype=F32, a/b=BF16, N=256, M=128

__device__ __forceinline__ uint32_t elect1() {
    uint32_t p;
    asm volatile("{ .reg .pred p; elect.sync _|p, 0xFFFFFFFF; selp.b32 %0,1,0,p; }"
                 : "=r"(p));
    return p;
}
#define MBAR_INIT(a, cnt) \
    asm volatile("mbarrier.init.shared.b64 [%0], %1;" :: "r"(a), "r"(cnt) : "memory")
#define MBAR_INVAL(a) \
    asm volatile("mbarrier.inval.shared.b64 [%0];" :: "r"(a) : "memory")
#define MBAR_WAIT(a, par) do {                                                   \
    uint32_t _m = (a), _p = (par), _d;                                           \
    asm volatile("{ .reg .pred p; mbarrier.try_wait.parity.acquire.cta.shared::cta.b64 p, [%1], %2; selp.b32 %0,1,0,p; }" \
        : "=r"(_d) : "r"(_m), "r"(_p) : "memory");                               \
    if (!_d) {                                                                   \
        asm volatile("{ .reg .pred P1; WL%=:"                                    \
            " mbarrier.try_wait.parity.acquire.cta.shared::cta.b64 P1, [%0], %1, 0x989680;" \
            " @P1 bra.uni WD%=; bra.uni WL%=; WD%=: }"                           \
            :: "r"(_m), "r"(_p) : "memory");                                     \
    }                                                                            \
} while (0)

#define TM_ALLOC(sa, n) \
    asm volatile("tcgen05.alloc.cta_group::1.sync.aligned.shared::cta.b32 [%0], %1;" :: "r"(sa), "r"(n) : "memory")
#define TM_RELINQ() \
    asm volatile("tcgen05.relinquish_alloc_permit.cta_group::1.sync.aligned;")
#define TM_DEALLOC(t, n) \
    asm volatile("tcgen05.dealloc.cta_group::1.sync.aligned.b32 %0, %1;" :: "r"(t), "r"(n))
#define TM_COMMIT(mb) \
    asm volatile("tcgen05.commit.cta_group::1.mbarrier::arrive::one.shared::cluster.b64 [%0];" :: "r"(mb) : "memory")
#define TM_FENCE_AFTER()  asm volatile("tcgen05.fence::after_thread_sync;" ::: "memory")
#define TM_FENCE_BEFORE() asm volatile("tcgen05.fence::before_thread_sync;" ::: "memory")
#define TM_WAIT_LD()      asm volatile("tcgen05.wait::ld.sync.aligned;" ::: "memory")

#define LDTM_X32(r, addr) \
    asm volatile( \
        "tcgen05.ld.sync.aligned.32x32b.x32.b32 " \
        "{%0,%1,%2,%3,%4,%5,%6,%7,%8,%9,%10,%11,%12,%13,%14,%15," \
        "%16,%17,%18,%19,%20,%21,%22,%23,%24,%25,%26,%27,%28,%29,%30,%31}, [%32];" \
        : "=r"((r)[0]),"=r"((r)[1]),"=r"((r)[2]),"=r"((r)[3]), \
          "=r"((r)[4]),"=r"((r)[5]),"=r"((r)[6]),"=r"((r)[7]), \
          "=r"((r)[8]),"=r"((r)[9]),"=r"((r)[10]),"=r"((r)[11]), \
          "=r"((r)[12]),"=r"((r)[13]),"=r"((r)[14]),"=r"((r)[15]), \
          "=r"((r)[16]),"=r"((r)[17]),"=r"((r)[18]),"=r"((r)[19]), \
          "=r"((r)[20]),"=r"((r)[21]),"=r"((r)[22]),"=r"((r)[23]), \
          "=r"((r)[24]),"=r"((r)[25]),"=r"((r)[26]),"=r"((r)[27]), \
          "=r"((r)[28]),"=r"((r)[29]),"=r"((r)[30]),"=r"((r)[31]) \
        : "r"(addr))

__device__ __forceinline__ uint64_t mk_desc(uint32_t addr) {
    const uint64_t BASE = (2ULL << 61) | (1ULL << 46) | (64ULL << 32) | (1ULL << 16);
    return BASE | (uint64_t)((addr >> 4) & 0x3FFF);
}
__device__ __forceinline__ void mma_ss(uint32_t d, uint64_t a, uint64_t b, uint32_t en) {
    asm volatile(
        "{\n\t.reg .pred p;\n\tsetp.ne.u32 p, %3, 0;\n\t"
        "tcgen05.mma.cta_group::1.kind::f16 [%0], %1, %2, %4, {%5,%5,%5,%5}, p;\n\t}"
        :: "r"(d), "l"(a), "l"(b), "r"(en), "r"(IDESC), "r"(0u) : "memory");
}

__global__ void __launch_bounds__(256, 1) sim_kernel(const float* __restrict__ db) {
    extern __shared__ char smem[];
    const uint32_t sb = smem_u32(smem);
    const int tid = threadIdx.x;
    const int wid = tid >> 5;
    const int q0 = (blockIdx.x & 1) * 128;
    const int n0 = (blockIdx.x >> 1) * TILE_N;

    if (tid == 0) { MBAR_INIT(sb + SM_MBAR0, 1); MBAR_INIT(sb + SM_MBAR1, 1); }
    if (wid == 0) { TM_ALLOC(sb + SM_TMEM, 256); TM_RELINQ(); }
    __syncthreads();
    uint32_t tmem;
    asm volatile("ld.shared.b32 %0,[%1];" : "=r"(tmem) : "r"(sb + SM_TMEM));

    float ps[16];
#pragma unroll
    for (int v = 0; v < 16; v++) ps[v] = 0.f;
    const int g  = tid >> 4;
    const int cs = tid & 15;

#pragma unroll 1
    for (int c = 0; c < NCHUNK; c++) {
        const int bufo = SM_BUF + (c & 1) * BUF_SIZE;
        char* buf = smem + bufo;
        if (c >= 2) {
            MBAR_WAIT(sb + ((c & 1) ? SM_MBAR1 : SM_MBAR0), ((c >> 1) - 1) & 1);
        }
        const int k0 = c * KC;

        // query tile (bf16, 128 rows x 64 k)
#pragma unroll
        for (int v = 0; v < 4; v++) {
            int ii  = (tid + 256 * v) & 1023;
            int row = ii >> 3, c16 = ii & 7;
            uint4 val = *(const uint4*)(g_qh + (size_t)(q0 + row) * Dk + k0 + c16 * 8);
            uint32_t off = (uint32_t)(row * 128 + c16 * 16);
            uint32_t sw  = off ^ ((off >> 3) & 0x70);
            *(uint4*)(buf + BUF_QH + sw) = val;
        }
        // db tile: fp32 -> bf16 hi, fuse norms
        {
            const float* dbase = db + (size_t)n0 * Dk + k0;
#pragma unroll
            for (int v = 0; v < 16; v++) {
                int row = g + 16 * v;
                float4 f = *(const float4*)(dbase + (size_t)row * Dk + cs * 4);
                ps[v] = fmaf(f.x, f.x, fmaf(f.y, f.y, fmaf(f.z, f.z, fmaf(f.w, f.w, ps[v]))));
                __nv_bfloat162 h01 = __floats2bfloat162_rn(f.x, f.y);
                __nv_bfloat162 h23 = __floats2bfloat162_rn(f.z, f.w);
                uint32_t off = (uint32_t)(row * 128 + cs * 8);
                uint32_t sw  = off ^ ((off >> 3) & 0x70);
                *(uint2*)(buf + BUF_DH + sw) = make_uint2(b2u(h01), b2u(h23));
            }
        }
        asm volatile("fence.proxy.async.shared::cta;" ::: "memory");
        __syncthreads();

        if (wid == 0 && elect1()) {
            const uint32_t sbuf = sb + bufo;
            uint64_t aH = mk_desc(sbuf + BUF_QH);
            uint64_t bH = mk_desc(sbuf + BUF_DH);
#pragma unroll
            for (int k = 0; k < 4; k++) mma_ss(tmem, aH + 2 * k, bH + 2 * k, (c | k) != 0);
            TM_COMMIT(sb + ((c & 1) ? SM_MBAR1 : SM_MBAR0));
        }
    }

    float* s_invn = (float*)(smem + SM_INVN);
#pragma unroll
    for (int v = 0; v < 16; v++) {
        float s = ps[v];
        s += __shfl_xor_sync(0xffffffffu, s, 1);
        s += __shfl_xor_sync(0xffffffffu, s, 2);
        s += __shfl_xor_sync(0xffffffffu, s, 4);
        s += __shfl_xor_sync(0xffffffffu, s, 8);
        if (cs == 0) {
            float r = 1.0f / fmaxf(sqrtf(s), 1e-8f);
            s_invn[g + 16 * v] = r;
            g_invn[n0 + g + 16 * v] = r;   // duplicate write identical across q-halves
        }
    }

    MBAR_WAIT(sb + SM_MBAR0, 1);
    MBAR_WAIT(sb + SM_MBAR1, 1);
    TM_FENCE_AFTER();
    __syncthreads();

    const int lane = tid & 31;
    const int q    = q0 + (wid & 3) * 32 + lane;
    const int cb   = (wid >> 2) * 128;
    unsigned long long best = 0ull;
    __nv_bfloat16* srow = g_sims + (size_t)q * Nn + n0;
#pragma unroll
    for (int i = 0; i < 4; i++) {
        uint32_t r[32];
        LDTM_X32(r, tmem + cb + 32 * i);
        TM_WAIT_LD();
#pragma unroll
        for (int j = 0; j < 32; j += 2) {
            int col = cb + 32 * i + j;
            float v0 = __uint_as_float(r[j])     * s_invn[col];
            float v1 = __uint_as_float(r[j + 1]) * s_invn[col + 1];
            unsigned long long c0 = pack_key(v0, (unsigned)(n0 + col));
            unsigned long long c1 = pack_key(v1, (unsigned)(n0 + col + 1));
            best = (c0 > best) ? c0 : best;
            best = (c1 > best) ? c1 : best;
            __nv_bfloat162 hv = __floats2bfloat162_rn(v0, v1);
            *(uint32_t*)(srow + col) = b2u(hv);
        }
    }
    TM_FENCE_BEFORE();
    atomicMax(&g_best[q], best);

    __syncthreads();
    if (tid == 0) { MBAR_INVAL(sb + SM_MBAR0); MBAR_INVAL(sb + SM_MBAR1); }
    if (wid == 0) { TM_DEALLOC(tmem, 256); }
}

#else
// ============================================================================
// Fallback path: mma.sync.m16n8k16 bf16 1-term
// ============================================================================
#define F_QH   0
#define F_DH   36864
#define F_BUF  73728
#define F_INVN 147456

__device__ __forceinline__ void ldsm_x4(uint32_t* r, uint32_t a) {
    asm volatile("ldmatrix.sync.aligned.m8n8.x4.shared.b16 {%0,%1,%2,%3}, [%4];"
                 : "=r"(r[0]), "=r"(r[1]), "=r"(r[2]), "=r"(r[3]) : "r"(a));
}
__device__ __forceinline__ void mma16816(float* d, const uint32_t* a, const uint32_t* b) {
    asm volatile(
        "mma.sync.aligned.m16n8k16.row.col.f32.bf16.bf16.f32 "
        "{%0,%1,%2,%3},{%4,%5,%6,%7},{%8,%9},{%0,%1,%2,%3};"
        : "+f"(d[0]), "+f"(d[1]), "+f"(d[2]), "+f"(d[3])
        : "r"(a[0]), "r"(a[1]), "r"(a[2]), "r"(a[3]), "r"(b[0]), "r"(b[1]));
}

__global__ void __launch_bounds__(256, 1) sim_kernel(const float* __restrict__ db) {
    extern __shared__ char smem[];
    const uint32_t sb32 = smem_u32(smem);
    const int tid  = threadIdx.x;
    const int lane = tid & 31;
    const int w    = tid >> 5;
    const int q0   = (blockIdx.x & 1) * 128;
    const int n0   = (blockIdx.x >> 1) * 256;
    const int qb   = (w & 3) * 32;
    const int nb   = (w >> 2) * 64;
    float* s_invn  = (float*)(smem + F_INVN);

    unsigned long long best[2][2] = {{0ull, 0ull}, {0ull, 0ull}};

#pragma unroll 1
    for (int nh = 0; nh < 2; nh++) {
        const int nbase = n0 + nh * 128;
        float acc[2][8][4];
#pragma unroll
        for (int a = 0; a < 2; a++)
#pragma unroll
            for (int b = 0; b < 8; b++)
#pragma unroll
                for (int r = 0; r < 4; r++) acc[a][b][r] = 0.f;
        float ps = 0.f;
        const int row  = tid >> 1;
        const int half = tid & 1;

#pragma unroll 1
        for (int c = 0; c < 12; c++) {
            const int bufo = (c & 1) * F_BUF;
            const int k0 = c * 64;
            {
                const uint4* qh = (const uint4*)(g_qh + (size_t)(q0 + row) * Dk + k0 + half * 32);
                char* dh = smem + bufo + F_QH + row * 144 + half * 64;
#pragma unroll
                for (int i = 0; i < 4; i++) ((uint4*)dh)[i] = qh[i];
            }
            {
                const float4* dsrc = (const float4*)(db + (size_t)(nbase + row) * Dk + k0 + half * 32);
                char* ph = smem + bufo + F_DH + row * 144 + half * 64;
#pragma unroll
                for (int i = 0; i < 8; i++) {
                    float4 f = dsrc[i];
                    ps = fmaf(f.x, f.x, fmaf(f.y, f.y, fmaf(f.z, f.z, fmaf(f.w, f.w, ps))));
                    __nv_bfloat162 h01 = __floats2bfloat162_rn(f.x, f.y);
                    __nv_bfloat162 h23 = __floats2bfloat162_rn(f.z, f.w);
                    *(uint2*)(ph + i * 8) = make_uint2(b2u(h01), b2u(h23));
                }
            }
            __syncthreads();

            const uint32_t sqh = sb32 + bufo + F_QH;
            const uint32_t sdh = sb32 + bufo + F_DH;
#pragma unroll
            for (int ks = 0; ks < 4; ks++) {
                uint32_t aH[2][4];
#pragma unroll
                for (int mi = 0; mi < 2; mi++) {
                    uint32_t ao = (uint32_t)((qb + mi * 16 + (lane & 15)) * 144 +
                                             ks * 32 + (lane >> 4) * 16);
                    ldsm_x4(aH[mi], sqh + ao);
                }
#pragma unroll
                for (int nip = 0; nip < 4; nip++) {
                    uint32_t bo = (uint32_t)((nb + nip * 16 + (lane & 7) +
                                              ((lane >> 4) & 1) * 8) * 144 +
                                             ks * 32 + ((lane >> 3) & 1) * 16);
                    uint32_t bh[4];
                    ldsm_x4(bh, sdh + bo);
#pragma unroll
                    for (int mi = 0; mi < 2; mi++)
#pragma unroll
                        for (int s = 0; s < 2; s++)
                            mma16816(acc[mi][nip * 2 + s], aH[mi], &bh[2 * s]);
                }
            }
        }
        {
            float s = ps + __shfl_xor_sync(0xffffffffu, ps, 1);
            if (!(tid & 1)) {
                float r = 1.0f / fmaxf(sqrtf(s), 1e-8f);
                s_invn[row] = r;
                g_invn[nbase + row] = r;
            }
        }
        __syncthreads();
#pragma unroll
        for (int mi = 0; mi < 2; mi++)
#pragma unroll
            for (int g8 = 0; g8 < 2; g8++) {
                const int q = q0 + qb + mi * 16 + g8 * 8 + (lane >> 2);
                __nv_bfloat16* srow = g_sims + (size_t)q * Nn + nbase;
                unsigned long long b = best[mi][g8];
#pragma unroll
                for (int ni = 0; ni < 8; ni++) {
                    int nl0 = nb + ni * 8 + (lane & 3) * 2;
                    float v0 = acc[mi][ni][g8 * 2 + 0] * s_invn[nl0];
                    float v1 = acc[mi][ni][g8 * 2 + 1] * s_invn[nl0 + 1];
                    unsigned long long c0 = pack_key(v0, (unsigned)(nbase + nl0));
                    unsigned long long c1 = pack_key(v1, (unsigned)(nbase + nl0 + 1));
                    b = (c0 > b) ? c0 : b;
                    b = (c1 > b) ? c1 : b;
                    __nv_bfloat162 hv = __floats2bfloat162_rn(v0, v1);
                    *(uint32_t*)(srow + nl0) = b2u(hv);
                }
                best[mi][g8] = b;
            }
        __syncthreads();
    }

#pragma unroll
    for (int mi = 0; mi < 2; mi++)
#pragma unroll
        for (int g8 = 0; g8 < 2; g8++) {
            unsigned long long b = best[mi][g8];
            unsigned long long o;
            o = __shfl_xor_sync(0xffffffffu, b, 1); b = (o > b) ? o : b;
            o = __shfl_xor_sync(0xffffffffu, b, 2); b = (o > b) ? o : b;
            if ((lane & 3) == 0) {
                int q = q0 + qb + mi * 16 + g8 * 8 + (lane >> 2);
                atomicMax(&g_best[q], b);
            }
        }
}
#endif  // USE_TCGEN05

// ---------------- pass 2: threshold scan + exact fp32 rescore ----------------
__device__ float dot768(const float* __restrict__ a, const float* __restrict__ b) {
    const float4* A = (const float4*)a;
    const float4* B = (const float4*)b;
    float s0 = 0.f, s1 = 0.f, s2 = 0.f, s3 = 0.f;
#pragma unroll 4
    for (int i = 0; i < 192; i += 4) {
        float4 a0 = A[i],     b0 = B[i];
        float4 a1 = A[i + 1], b1 = B[i + 1];
        float4 a2 = A[i + 2], b2 = B[i + 2];
        float4 a3 = A[i + 3], b3 = B[i + 3];
        s0 = fmaf(a0.x, b0.x, fmaf(a0.y, b0.y, fmaf(a0.z, b0.z, fmaf(a0.w, b0.w, s0))));
        s1 = fmaf(a1.x, b1.x, fmaf(a1.y, b1.y, fmaf(a1.z, b1.z, fmaf(a1.w, b1.w, s1))));
        s2 = fmaf(a2.x, b2.x, fmaf(a2.y, b2.y, fmaf(a2.z, b2.z, fmaf(a2.w, b2.w, s2))));
        s3 = fmaf(a3.x, b3.x, fmaf(a3.y, b3.y, fmaf(a3.z, b3.z, fmaf(a3.w, b3.w, s3))));
    }
    return (s0 + s1) + (s2 + s3);
}

__global__ void __launch_bounds__(256) scan_kernel(const float* __restrict__ x,
                                                   const float* __restrict__ db) {
    const int q = blockIdx.x;
    const int tid = threadIdx.x;
    __shared__ unsigned long long s_red[256];

    const float thr = unpack_val(g_best[q]) - 1.0f;   // >=250 sigma of bf16 error
    const __nv_bfloat16* srow = g_sims + (size_t)q * Nn;
    const float* xq = x + (size_t)q * Dk;

    unsigned long long best = 0ull;
    for (int i = tid; i < Nn / 8; i += 256) {
        uint4 v = ((const uint4*)srow)[i];
        unsigned u[4] = {v.x, v.y, v.z, v.w};
#pragma unroll
        for (int j = 0; j < 4; j++) {
            __nv_bfloat162 h = *(__nv_bfloat162*)&u[j];
            float f0 = __low2float(h), f1 = __high2float(h);
            if (f0 >= thr) {
                int n = i * 8 + j * 2;
                float e = dot768(xq, db + (size_t)n * Dk) * g_invn[n];
                unsigned long long c = pack_key(e, (unsigned)n);
                best = (c > best) ? c : best;
            }
            if (f1 >= thr) {
                int n = i * 8 + j * 2 + 1;
                float e = dot768(xq, db + (size_t)n * Dk) * g_invn[n];
                unsigned long long c = pack_key(e, (unsigned)n);
                best = (c > best) ? c : best;
            }
        }
    }
    s_red[tid] = best;
    __syncthreads();
#pragma unroll
    for (int s = 128; s; s >>= 1) {
        if (tid < s) {
            unsigned long long o = s_red[tid + s];
            if (o > s_red[tid]) s_red[tid] = o;
        }
        __syncthreads();
    }
    if (tid == 0) g_best2[q] = s_red[0];
}

// ---------------- gather ----------------
__global__ void gather_kernel(const float* __restrict__ y, float* __restrict__ out) {
    const int b = blockIdx.x;
    unsigned idx = ~((unsigned)(g_best2[b] & 0xffffffffull));
    const float4* src = (const float4*)(y + (size_t)idx * Lo);
    float4* dst = (float4*)(out + (size_t)b * Lo);
    dst[threadIdx.x] = src[threadIdx.x];
}

extern "C" void kernel_launch(void* const* d_in, const int* in_sizes, int n_in,
                              void* d_out, int out_size) {
    const float* imu = (const float*)d_in[0];
    const float* dbx = (const float*)d_in[1];
    const float* dby = (const float*)d_in[2];
    float* out = (float*)d_out;

    cudaFuncSetAttribute(sim_kernel, cudaFuncAttributeMaxDynamicSharedMemorySize,
                         SMEM_TOTAL);

    init_kernel<<<1, Bq>>>();
    convert_q_kernel<<<Dk, 256>>>(imu);
    sim_kernel<<<1024, 256, SMEM_TOTAL>>>(dbx);
    scan_kernel<<<Bq, 256>>>(imu, dbx);
    gather_kernel<<<Bq, Lo / 4>>>(dby, out);
}

// round 5
// speedup vs baseline: 3.0214x; 3.0214x over previous
#include <cuda_runtime.h>
#include <cuda_bf16.h>
#include <cstdint>

#define Bq 256      // queries
#define Dk 768      // feature dim
#define Nn 131072   // database rows
#define Lo 512      // output row length

#define MARGIN 0.4f
#define CAND_CAP (1 << 20)

// smem layout (per buffer: q tile 128x72 bf16 = 18432 B, db tile 128x72 bf16 = 18432 B)
#define F_QH   0
#define F_DH   18432
#define F_BUF  36864
#define F_INVN 73728
#define SMEM_TOTAL (F_INVN + 512 + 128)

__device__ __nv_bfloat16 g_qh[Bq * Dk];
__device__ float g_invn[Nn];
__device__ unsigned g_best[Bq];                 // sortable-float running max (threshold)
__device__ unsigned long long g_best2[Bq];      // exact argmax keys
__device__ int g_cand_count;
__device__ unsigned g_cand[CAND_CAP];           // (q << 17) | n

// ---------------- helpers ----------------
__device__ __forceinline__ uint32_t smem_u32(const void* p) {
    uint32_t a;
    asm("{ .reg .u64 t; cvta.to.shared.u64 t, %1; cvt.u32.u64 %0, t; }"
        : "=r"(a) : "l"(p));
    return a;
}
__device__ __forceinline__ unsigned sortable32(float v) {
    unsigned u = __float_as_uint(v);
    return (u & 0x80000000u) ? ~u : (u | 0x80000000u);
}
__device__ __forceinline__ float unsortable32(unsigned s) {
    unsigned u = (s & 0x80000000u) ? (s & 0x7fffffffu) : ~s;
    return __uint_as_float(u);
}
__device__ __forceinline__ unsigned long long pack_key(float v, unsigned idx) {
    return ((unsigned long long)sortable32(v) << 32) | (unsigned)(~idx);
}
__device__ __forceinline__ uint32_t b2u(__nv_bfloat162 h) {
    return *reinterpret_cast<uint32_t*>(&h);
}
__device__ __forceinline__ void cp_async16(uint32_t dst, const void* src) {
    asm volatile("cp.async.ca.shared.global [%0], [%1], 16;"
                 :: "r"(dst), "l"(src) : "memory");
}
__device__ __forceinline__ void cp_commit() {
    asm volatile("cp.async.commit_group;" ::: "memory");
}
__device__ __forceinline__ void cp_wait_all() {
    asm volatile("cp.async.wait_group 0;" ::: "memory");
}
__device__ __forceinline__ void ldsm_x4(uint32_t* r, uint32_t a) {
    asm volatile("ldmatrix.sync.aligned.m8n8.x4.shared.b16 {%0,%1,%2,%3}, [%4];"
                 : "=r"(r[0]), "=r"(r[1]), "=r"(r[2]), "=r"(r[3]) : "r"(a));
}
__device__ __forceinline__ void mma16816(float* d, const uint32_t* a, const uint32_t* b) {
    asm volatile(
        "mma.sync.aligned.m16n8k16.row.col.f32.bf16.bf16.f32 "
        "{%0,%1,%2,%3},{%4,%5,%6,%7},{%8,%9},{%0,%1,%2,%3};"
        : "+f"(d[0]), "+f"(d[1]), "+f"(d[2]), "+f"(d[3])
        : "r"(a[0]), "r"(a[1]), "r"(a[2]), "r"(a[3]), "r"(b[0]), "r"(b[1]));
}

// ---------------- convert queries + init state ----------------
__global__ void convert_init_kernel(const float* __restrict__ x) {
    int i = blockIdx.x * 256 + threadIdx.x;
    g_qh[i] = __float2bfloat16(x[i]);
    if (blockIdx.x == 0) {
        g_best[threadIdx.x] = 0u;
        g_best2[threadIdx.x] = 0ull;
        if (threadIdx.x == 0) g_cand_count = 0;
    }
}

// ---------------- pass 1: bf16 GEMM + running-max candidate emission ----------------
__global__ void __launch_bounds__(256, 2) sim_kernel(const float* __restrict__ db) {
    extern __shared__ char smem[];
    const uint32_t sb32 = smem_u32(smem);
    const int tid  = threadIdx.x;
    const int lane = tid & 31;
    const int w    = tid >> 5;
    const int q0   = (blockIdx.x & 1) * 128;
    const int n0   = (blockIdx.x >> 1) * 256;
    const int qb   = (w & 3) * 32;     // 32 queries per warp group
    const int nb   = (w >> 2) * 64;    // 64 db rows per warp group
    float* s_invn  = (float*)(smem + F_INVN);

    const int row  = tid >> 1;         // 0..127
    const int half = tid & 1;

#pragma unroll 1
    for (int nh = 0; nh < 2; nh++) {
        const int nbase = n0 + nh * 128;
        float acc[2][8][4];
#pragma unroll
        for (int a = 0; a < 2; a++)
#pragma unroll
            for (int b = 0; b < 8; b++)
#pragma unroll
                for (int r = 0; r < 4; r++) acc[a][b][r] = 0.f;
        float ps = 0.f;

        // ---- prologue: prefetch chunk 0 ----
        float4 dreg[8];
        {
            const float4* dsrc = (const float4*)(db + (size_t)(nbase + row) * Dk + half * 32);
#pragma unroll
            for (int i = 0; i < 8; i++) dreg[i] = dsrc[i];
            const __nv_bfloat16* qsrc = g_qh + (size_t)(q0 + row) * Dk + half * 32;
            uint32_t qdst = sb32 + F_QH + row * 144 + half * 64;
#pragma unroll
            for (int i = 0; i < 4; i++) cp_async16(qdst + i * 16, qsrc + i * 8);
            cp_commit();
        }

#pragma unroll 1
        for (int c = 0; c < 12; c++) {
            const int bufo = (c & 1) * F_BUF;
            // 1. convert & store db chunk c from regs; fuse norms
            {
                char* ph = smem + bufo + F_DH + row * 144 + half * 64;
#pragma unroll
                for (int i = 0; i < 8; i++) {
                    float4 f = dreg[i];
                    ps = fmaf(f.x, f.x, fmaf(f.y, f.y, fmaf(f.z, f.z, fmaf(f.w, f.w, ps))));
                    __nv_bfloat162 h01 = __floats2bfloat162_rn(f.x, f.y);
                    __nv_bfloat162 h23 = __floats2bfloat162_rn(f.z, f.w);
                    *(uint2*)(ph + i * 8) = make_uint2(b2u(h01), b2u(h23));
                }
            }
            // 2. prefetch db chunk c+1 into regs
            if (c < 11) {
                const float4* dsrc = (const float4*)(db + (size_t)(nbase + row) * Dk +
                                                     (c + 1) * 64 + half * 32);
#pragma unroll
                for (int i = 0; i < 8; i++) dreg[i] = dsrc[i];
            }
            // 3. q chunk c arrived
            cp_wait_all();
            // 4. tiles for chunk c complete across CTA
            __syncthreads();
            // 5. prefetch q chunk c+1 (safe: all warps done with buf[(c+1)&1])
            if (c < 11) {
                const __nv_bfloat16* qsrc = g_qh + (size_t)(q0 + row) * Dk +
                                            (c + 1) * 64 + half * 32;
                uint32_t qdst = sb32 + ((c + 1) & 1) * F_BUF + F_QH + row * 144 + half * 64;
#pragma unroll
                for (int i = 0; i < 4; i++) cp_async16(qdst + i * 16, qsrc + i * 8);
                cp_commit();
            }
            // 6. MMA on chunk c
            const uint32_t sqh = sb32 + bufo + F_QH;
            const uint32_t sdh = sb32 + bufo + F_DH;
#pragma unroll
            for (int ks = 0; ks < 4; ks++) {
                uint32_t aH[2][4];
#pragma unroll
                for (int mi = 0; mi < 2; mi++) {
                    uint32_t ao = (uint32_t)((qb + mi * 16 + (lane & 15)) * 144 +
                                             ks * 32 + (lane >> 4) * 16);
                    ldsm_x4(aH[mi], sqh + ao);
                }
#pragma unroll
                for (int nip = 0; nip < 4; nip++) {
                    uint32_t bo = (uint32_t)((nb + nip * 16 + (lane & 7) +
                                              ((lane >> 4) & 1) * 8) * 144 +
                                             ks * 32 + ((lane >> 3) & 1) * 16);
                    uint32_t bh[4];
                    ldsm_x4(bh, sdh + bo);
#pragma unroll
                    for (int mi = 0; mi < 2; mi++)
#pragma unroll
                        for (int s = 0; s < 2; s++)
                            mma16816(acc[mi][nip * 2 + s], aH[mi], &bh[2 * s]);
                }
            }
        }
        // fence MMA reads of both buffers before epilogue reuses smem / next nh overwrites
        __syncthreads();

        // ---- inverse norms for this n-half ----
        {
            float s = ps + __shfl_xor_sync(0xffffffffu, ps, 1);
            if (!half) {
                float r = 1.0f / fmaxf(sqrtf(s), 1e-8f);
                s_invn[row] = r;
                g_invn[nbase + row] = r;
            }
        }
        __syncthreads();

        // ---- scale accs, fold per-q max, update running global, emit candidates ----
#pragma unroll
        for (int mi = 0; mi < 2; mi++)
#pragma unroll
            for (int g8 = 0; g8 < 2; g8++) {
                const int q = q0 + qb + mi * 16 + g8 * 8 + (lane >> 2);
                float m = -1e30f;
#pragma unroll
                for (int ni = 0; ni < 8; ni++)
#pragma unroll
                    for (int s = 0; s < 2; s++) {
                        int nl = nb + ni * 8 + (lane & 3) * 2 + s;
                        float v = acc[mi][ni][g8 * 2 + s] * s_invn[nl];
                        acc[mi][ni][g8 * 2 + s] = v;
                        m = fmaxf(m, v);
                    }
                // max over the 4 lanes sharing q
                m = fmaxf(m, __shfl_xor_sync(0xffffffffu, m, 1));
                m = fmaxf(m, __shfl_xor_sync(0xffffffffu, m, 2));
                unsigned cur;
                if ((lane & 3) == 0) {
                    unsigned old = atomicMax(&g_best[q], sortable32(m));
                    cur = max(old, sortable32(m));
                }
                cur = __shfl_sync(0xffffffffu, cur, lane & 28);
                float thr = unsortable32(cur) - MARGIN;
#pragma unroll
                for (int ni = 0; ni < 8; ni++)
#pragma unroll
                    for (int s = 0; s < 2; s++) {
                        float v = acc[mi][ni][g8 * 2 + s];
                        if (v >= thr) {
                            int n = nbase + nb + ni * 8 + (lane & 3) * 2 + s;
                            int slot = atomicAdd(&g_cand_count, 1);
                            if (slot < CAND_CAP)
                                g_cand[slot] = ((unsigned)q << 17) | (unsigned)n;
                        }
                    }
            }
        __syncthreads();
    }
}

// ---------------- pass 2: exact fp32 rescore of candidates ----------------
__global__ void __launch_bounds__(128) rescore_kernel(const float* __restrict__ x,
                                                      const float* __restrict__ db) {
    __shared__ float s_part[4];
    const int tid = threadIdx.x;
    int cnt = g_cand_count;
    if (cnt > CAND_CAP) cnt = CAND_CAP;

    for (int i = blockIdx.x; i < cnt; i += gridDim.x) {
        unsigned p = g_cand[i];
        unsigned q = p >> 17;
        unsigned n = p & 0x1FFFFu;
        const float* xq = x + (size_t)q * Dk;
        const float* dn = db + (size_t)n * Dk;
        float s = 0.f;
#pragma unroll
        for (int j = 0; j < 6; j++)
            s = fmaf(xq[tid + 128 * j], dn[tid + 128 * j], s);
#pragma unroll
        for (int m = 16; m; m >>= 1) s += __shfl_xor_sync(0xffffffffu, s, m);
        if ((tid & 31) == 0) s_part[tid >> 5] = s;
        __syncthreads();
        if (tid == 0) {
            float v = (s_part[0] + s_part[1] + s_part[2] + s_part[3]) * g_invn[n];
            atomicMax(&g_best2[q], pack_key(v, n));
        }
        __syncthreads();
    }
}

// ---------------- gather ----------------
__global__ void gather_kernel(const float* __restrict__ y, float* __restrict__ out) {
    const int b = blockIdx.x;
    unsigned idx = ~((unsigned)(g_best2[b] & 0xffffffffull));
    const float4* src = (const float4*)(y + (size_t)idx * Lo);
    float4* dst = (float4*)(out + (size_t)b * Lo);
    dst[threadIdx.x] = src[threadIdx.x];
}

extern "C" void kernel_launch(void* const* d_in, const int* in_sizes, int n_in,
                              void* d_out, int out_size) {
    const float* imu = (const float*)d_in[0];
    const float* dbx = (const float*)d_in[1];
    const float* dby = (const float*)d_in[2];
    float* out = (float*)d_out;

    cudaFuncSetAttribute(sim_kernel, cudaFuncAttributeMaxDynamicSharedMemorySize,
                         SMEM_TOTAL);

    convert_init_kernel<<<Dk, 256>>>(imu);
    sim_kernel<<<1024, 256, SMEM_TOTAL>>>(dbx);
    rescore_kernel<<<1024, 128>>>(imu, dbx);
    gather_kernel<<<Bq, Lo / 4>>>(dby, out);
}